// round 14
// baseline (speedup 1.0000x reference)
#include <cuda_runtime.h>
#include <cuda_fp16.h>

// Problem-fixed dims: N=100000, E=1600000, IN=128, H=64, OUT=32
#define MAXN 100000
#define MAXE 1600000
#define IN_DIM 128
#define H_DIM 64
#define OUT_DIM 32
#define SCAN_B 1024
#define MAX_BLK ((MAXN + SCAN_B - 1) / SCAN_B)   // 98
#define FUSE_BLOCKS 1024

typedef unsigned long long ull;

// ---------------- scratch (device globals; no allocation allowed) ------------
__device__ __align__(16) int   g_cnt [MAXN];   // in-degree (excl self-loop)
__device__ __align__(16) int   g_row [MAXN + 1];
__device__ __align__(16) int   g_cur [MAXN];
__device__ __align__(16) int   g_bsum[MAX_BLK];
__device__ __align__(16) int   g_boff[MAX_BLK];
__device__ __align__(16) float g_dinv[MAXN];
__device__ __align__(16) int2  g_csr [MAXE];   // (src, norm-bits) grouped by dst
__device__ __align__(16) __half g_Z1h[(size_t)MAXN * H_DIM]; // x@W1      (fp16)
__device__ __align__(16) __half g_Z2h[(size_t)MAXN * H_DIM]; // relu(h)@W (fp16)

// ---------------- bit-cast helpers -------------------------------------------
__device__ __forceinline__ unsigned h2u(__half2 h) {
    return *reinterpret_cast<unsigned*>(&h);
}
__device__ __forceinline__ __half2 u2h(unsigned u) {
    return *reinterpret_cast<__half2*>(&u);
}

// ---------------- f32x2 packed FMA helpers -----------------------------------
__device__ __forceinline__ ull pack_dup(float a) {
    ull r;
    asm("mov.b64 %0, {%1, %1};" : "=l"(r) : "r"(__float_as_uint(a)));
    return r;
}
#define FMA2(acc, a2, b2) \
    asm("fma.rn.f32x2 %0, %1, %2, %0;" : "+l"(acc) : "l"(a2), "l"(b2))

__device__ __forceinline__ float2 unpack2(ull v) {
    float2 f;
    asm("mov.b64 {%0, %1}, %2;" : "=f"(f.x), "=f"(f.y) : "l"(v));
    return f;
}

// ---------------- dtype probe helper (per-block, L2-hot, ~free) --------------
__device__ __forceinline__ int probe_is64(const int* __restrict__ raw, int E,
                                          int* sh_nz) {
    if (threadIdx.x == 0) *sh_nz = 0;
    __syncthreads();
    int K = 2048;
    if (K > 2 * E) K = 2 * E;
    int cnt = 0;
    for (int i = 2 * threadIdx.x + 1; i < K; i += 2 * blockDim.x)
        if (raw[i] != 0) cnt++;
    if (cnt) atomicAdd(sh_nz, cnt);
    __syncthreads();
    return (*sh_nz == 0);
}

// ---------------- zero counters ----------------------------------------------
__global__ void k_zero(int n) {
    int i = blockIdx.x * blockDim.x + threadIdx.x;
    if (i < n) g_cnt[i] = 0;
}

// ---------------- count in-degrees straight from raw edge list ---------------
__global__ __launch_bounds__(256) void k_count(const int* __restrict__ raw,
                                               int E, int n) {
    __shared__ int nz;
    int is64 = probe_is64(raw, E, &nz);
    int i = blockIdx.x * 256 + threadIdx.x;
    if (i >= E) return;
    int d = is64 ? (int)((const long long*)raw)[(size_t)E + i] : raw[E + i];
    if ((unsigned)d >= (unsigned)n) d = 0;
    atomicAdd(&g_cnt[d], 1);
}

// ---------------- hierarchical exclusive scan of g_cnt -----------------------
__global__ __launch_bounds__(SCAN_B) void k_scanA(int n) {
    __shared__ int sh[SCAN_B];
    int t = threadIdx.x;
    int i = blockIdx.x * SCAN_B + t;
    int v = (i < n) ? g_cnt[i] : 0;
    sh[t] = v;
    __syncthreads();
#pragma unroll
    for (int off = 1; off < SCAN_B; off <<= 1) {
        int u = (t >= off) ? sh[t - off] : 0;
        __syncthreads();
        sh[t] += u;
        __syncthreads();
    }
    if (i < n) g_row[i] = sh[t] - v;
    if (t == SCAN_B - 1) g_bsum[blockIdx.x] = sh[t];
}

__global__ __launch_bounds__(128) void k_scanB(int nblk, int n) {
    __shared__ int sh[128];
    int t = threadIdx.x;
    int v = (t < nblk) ? g_bsum[t] : 0;
    sh[t] = v;
    __syncthreads();
#pragma unroll
    for (int off = 1; off < 128; off <<= 1) {
        int u = (t >= off) ? sh[t - off] : 0;
        __syncthreads();
        sh[t] += u;
        __syncthreads();
    }
    if (t < nblk) g_boff[t] = sh[t] - v;
    if (t == 127) g_row[n] = sh[127];
}

// Phase C: add block offsets; mirror into g_cur; fused dinv.
__global__ __launch_bounds__(SCAN_B) void k_scanC(int n) {
    int i = blockIdx.x * SCAN_B + threadIdx.x;
    if (i < n) {
        int r = g_row[i] + g_boff[blockIdx.x];
        g_row[i] = r;
        g_cur[i] = r;
        g_dinv[i] = rsqrtf(1.0f + (float)g_cnt[i]);  // +1 self-loop
    }
}

// ---------------- scatter into CSR straight from raw (norm computed here) ----
__global__ __launch_bounds__(256) void k_scatter(const int* __restrict__ raw,
                                                 int E, int n) {
    __shared__ int nz;
    int is64 = probe_is64(raw, E, &nz);
    int i = blockIdx.x * 256 + threadIdx.x;
    if (i >= E) return;
    int s, d;
    if (is64) {
        const long long* e64 = (const long long*)raw;
        s = (int)e64[i];
        d = (int)e64[(size_t)E + i];
    } else {
        s = raw[i];
        d = raw[E + i];
    }
    if ((unsigned)s >= (unsigned)n) s = 0;
    if ((unsigned)d >= (unsigned)n) d = 0;
    float w = g_dinv[s] * g_dinv[d];
    int pos = atomicAdd(&g_cur[d], 1);
    g_csr[pos] = make_int2(s, __float_as_int(w));
}

// ---------------- GEMM1: Z1 = x @ W1, fp32 math, fp16 store ------------------
__global__ __launch_bounds__(256) void k_gemm1(const float* __restrict__ x,
                                               const float* __restrict__ W1, int n) {
    __shared__ __align__(16) float Bs[IN_DIM * H_DIM];  // 32 KB
    int tid = threadIdx.x;
    for (int i = tid; i < IN_DIM * H_DIM; i += 256) Bs[i] = W1[i];
    __syncthreads();
    int row = blockIdx.x * 256 + tid;
    if (row >= n) return;

    ull acc[32];   // 64 cols as 32 packed f32x2
#pragma unroll
    for (int i = 0; i < 32; i++) acc[i] = 0ull;

    const float4* arow = (const float4*)(x + (size_t)row * IN_DIM);
#pragma unroll 2
    for (int k4 = 0; k4 < IN_DIM / 4; k4++) {
        float4 a4 = arow[k4];
        float av[4] = {a4.x, a4.y, a4.z, a4.w};
#pragma unroll
        for (int kk = 0; kk < 4; kk++) {
            ull a2 = pack_dup(av[kk]);
            const ull* br = (const ull*)(Bs + (k4 * 4 + kk) * H_DIM);
#pragma unroll
            for (int c = 0; c < 32; c++) FMA2(acc[c], a2, br[c]);
        }
    }
    uint4* crow = (uint4*)(g_Z1h + (size_t)row * H_DIM);
#pragma unroll
    for (int q = 0; q < 8; q++) {
        uint4 v;
        float2 f0 = unpack2(acc[4 * q + 0]);
        float2 f1 = unpack2(acc[4 * q + 1]);
        float2 f2 = unpack2(acc[4 * q + 2]);
        float2 f3 = unpack2(acc[4 * q + 3]);
        v.x = h2u(__floats2half2_rn(f0.x, f0.y));
        v.y = h2u(__floats2half2_rn(f1.x, f1.y));
        v.z = h2u(__floats2half2_rn(f2.x, f2.y));
        v.w = h2u(__floats2half2_rn(f3.x, f3.y));
        crow[q] = v;
    }
}

// ---------------- FUSED agg1 + GEMM2: h in registers, Z2h out ----------------
// Warp loops over nodes (stride = total warps). Per node:
//   1) gather-aggregate h = b1 + dinv^2*Z1[v] + sum w*Z1[src]   (fp32 acc)
//   2) warp-level GEMM: Z2[v] = relu(h) @ [Wmu|Wlog], lane owns 2 cols
__global__ __launch_bounds__(256) void k_agg1_gemm2(const float* __restrict__ b1,
                                                    const float* __restrict__ Wmu,
                                                    const float* __restrict__ Wlog,
                                                    int n) {
    __shared__ __align__(16) float Bs[H_DIM * 64];  // [k][64]: 0..31 Wmu, 32..63 Wlog
    int tid = threadIdx.x;
    for (int i = tid; i < H_DIM * OUT_DIM; i += 256) {
        int k = i / OUT_DIM, c = i % OUT_DIM;
        Bs[k * 64 + c]      = Wmu[i];
        Bs[k * 64 + 32 + c] = Wlog[i];
    }
    __syncthreads();

    int gwarp  = (blockIdx.x * 256 + tid) >> 5;
    int nwarps = gridDim.x * 8;
    int lane = tid & 31;
    int half = lane >> 4, l16 = lane & 15;
    const uint2* zb = (const uint2*)g_Z1h;   // 4 halves per uint2

    for (int node = gwarp; node < n; node += nwarps) {
        int rs = g_row[node], re = g_row[node + 1];

        float4 acc;
        if (half == 0) {   // seed self-loop + bias once
            float dv = g_dinv[node];
            float s2 = dv * dv;
            uint2 z = zb[(size_t)node * 16 + l16];
            float2 f0 = __half22float2(u2h(z.x));
            float2 f1 = __half22float2(u2h(z.y));
            float4 b  = ((const float4*)b1)[l16];
            acc = make_float4(fmaf(f0.x, s2, b.x), fmaf(f0.y, s2, b.y),
                              fmaf(f1.x, s2, b.z), fmaf(f1.y, s2, b.w));
        } else {
            acc = make_float4(0.f, 0.f, 0.f, 0.f);
        }
        for (int e = rs + half; e < re; e += 2) {
            int2 ed = g_csr[e];
            float w = __int_as_float(ed.y);
            uint2 z = zb[(size_t)ed.x * 16 + l16];
            float2 f0 = __half22float2(u2h(z.x));
            float2 f1 = __half22float2(u2h(z.y));
            acc.x = fmaf(w, f0.x, acc.x);
            acc.y = fmaf(w, f0.y, acc.y);
            acc.z = fmaf(w, f1.x, acc.z);
            acc.w = fmaf(w, f1.y, acc.w);
        }
        // combine halves: afterwards ALL lanes hold h[4*l16 .. 4*l16+3]
        acc.x += __shfl_xor_sync(0xffffffffu, acc.x, 16);
        acc.y += __shfl_xor_sync(0xffffffffu, acc.y, 16);
        acc.z += __shfl_xor_sync(0xffffffffu, acc.z, 16);
        acc.w += __shfl_xor_sync(0xffffffffu, acc.w, 16);

        // warp GEMM: lane computes Z2 cols [2*lane, 2*lane+1]
        ull a2c = 0ull;
#pragma unroll
        for (int kq = 0; kq < 16; kq++) {
            float4 h4;
            h4.x = __shfl_sync(0xffffffffu, acc.x, kq);
            h4.y = __shfl_sync(0xffffffffu, acc.y, kq);
            h4.z = __shfl_sync(0xffffffffu, acc.z, kq);
            h4.w = __shfl_sync(0xffffffffu, acc.w, kq);
            h4.x = fmaxf(h4.x, 0.f);
            h4.y = fmaxf(h4.y, 0.f);
            h4.z = fmaxf(h4.z, 0.f);
            h4.w = fmaxf(h4.w, 0.f);
            FMA2(a2c, pack_dup(h4.x), *(const ull*)(Bs + (4 * kq + 0) * 64 + 2 * lane));
            FMA2(a2c, pack_dup(h4.y), *(const ull*)(Bs + (4 * kq + 1) * 64 + 2 * lane));
            FMA2(a2c, pack_dup(h4.z), *(const ull*)(Bs + (4 * kq + 2) * 64 + 2 * lane));
            FMA2(a2c, pack_dup(h4.w), *(const ull*)(Bs + (4 * kq + 3) * 64 + 2 * lane));
        }
        float2 f = unpack2(a2c);
        ((unsigned*)g_Z2h)[(size_t)node * 32 + lane] =
            h2u(__floats2half2_rn(f.x, f.y));
    }
}

// ---------------- CSR aggregation 2: warp/node, fp16 gather -> d_out ---------
__global__ __launch_bounds__(256) void k_agg2_csr(const float* __restrict__ bmu,
                                                  const float* __restrict__ blog,
                                                  float* __restrict__ outMu,
                                                  float* __restrict__ outLog, int n) {
    int warp = (blockIdx.x * 256 + threadIdx.x) >> 5;
    int lane = threadIdx.x & 31;
    if (warp >= n) return;
    int half = lane >> 4, l16 = lane & 15;
    int rs = g_row[warp], re = g_row[warp + 1];
    const uint2* zb = (const uint2*)g_Z2h;

    float4 acc;
    if (half == 0) {
        float dv = g_dinv[warp];
        float s2 = dv * dv;
        uint2 z = zb[(size_t)warp * 16 + l16];
        float2 f0 = __half22float2(u2h(z.x));
        float2 f1 = __half22float2(u2h(z.y));
        float4 b = (l16 < 8) ? ((const float4*)bmu)[l16]
                             : ((const float4*)blog)[l16 - 8];
        acc = make_float4(fmaf(f0.x, s2, b.x), fmaf(f0.y, s2, b.y),
                          fmaf(f1.x, s2, b.z), fmaf(f1.y, s2, b.w));
    } else {
        acc = make_float4(0.f, 0.f, 0.f, 0.f);
    }
    for (int e = rs + half; e < re; e += 2) {
        int2 ed = g_csr[e];
        float w = __int_as_float(ed.y);
        uint2 z = zb[(size_t)ed.x * 16 + l16];
        float2 f0 = __half22float2(u2h(z.x));
        float2 f1 = __half22float2(u2h(z.y));
        acc.x = fmaf(w, f0.x, acc.x);
        acc.y = fmaf(w, f0.y, acc.y);
        acc.z = fmaf(w, f1.x, acc.z);
        acc.w = fmaf(w, f1.y, acc.w);
    }
    acc.x += __shfl_xor_sync(0xffffffffu, acc.x, 16);
    acc.y += __shfl_xor_sync(0xffffffffu, acc.y, 16);
    acc.z += __shfl_xor_sync(0xffffffffu, acc.z, 16);
    acc.w += __shfl_xor_sync(0xffffffffu, acc.w, 16);
    if (half == 0) {
        if (l16 < 8)
            ((float4*)(outMu + (size_t)warp * OUT_DIM))[l16] = acc;
        else
            ((float4*)(outLog + (size_t)warp * OUT_DIM))[l16 - 8] = acc;
    }
}

// ---------------- launch -----------------------------------------------------
extern "C" void kernel_launch(void* const* d_in, const int* in_sizes, int n_in,
                              void* d_out, int out_size) {
    const float* x    = (const float*)d_in[0];
    const int*   eraw = (const int*)d_in[1];
    const float* W1   = (const float*)d_in[2];
    const float* b1   = (const float*)d_in[3];
    const float* Wmu  = (const float*)d_in[4];
    const float* bmu  = (const float*)d_in[5];
    const float* Wlog = (const float*)d_in[6];
    const float* blog = (const float*)d_in[7];

    int N = in_sizes[0] / IN_DIM;   // 100000
    int E = in_sizes[1] / 2;        // 1600000
    if (N > MAXN) N = MAXN;
    if (E > MAXE) E = MAXE;

    float* outMu  = (float*)d_out;
    float* outLog = (float*)d_out + (size_t)N * OUT_DIM;

    const int T = 256;
    int gN   = (N + T - 1) / T;
    int gE   = (E + T - 1) / T;
    int gW   = (N * 32 + T - 1) / T;          // warp-per-node grid (agg2)
    int nblk = (N + SCAN_B - 1) / SCAN_B;     // scan blocks (98)

    // Lazy side-stream + fork/join events (host objects only).
    static cudaStream_t s2 = nullptr;
    static cudaEvent_t  evFork = nullptr, evJoin = nullptr;
    if (s2 == nullptr) {
        cudaStreamCreateWithFlags(&s2, cudaStreamNonBlocking);
        cudaEventCreateWithFlags(&evFork, cudaEventDisableTiming);
        cudaEventCreateWithFlags(&evJoin, cudaEventDisableTiming);
    }

    // Fork: GEMM1 runs concurrently with the CSR build chain.
    cudaEventRecord(evFork, 0);
    cudaStreamWaitEvent(s2, evFork, 0);
    k_gemm1<<<gN, T, 0, s2>>>(x, W1, N);
    cudaEventRecord(evJoin, s2);

    // CSR build on the main stream
    k_zero<<<gN, T>>>(N);
    k_count<<<gE, T>>>(eraw, E, N);
    k_scanA<<<nblk, SCAN_B>>>(N);
    k_scanB<<<1, 128>>>(nblk, N);
    k_scanC<<<nblk, SCAN_B>>>(N);             // offsets + g_cur + dinv fused
    k_scatter<<<gE, T>>>(eraw, E, N);

    // Join: fused agg1+gemm2 needs both Z1 (s2) and CSR (main stream)
    cudaStreamWaitEvent(0, evJoin, 0);

    // layer 1 aggregation fused with layer-2 GEMM (h never leaves registers)
    k_agg1_gemm2<<<FUSE_BLOCKS, T>>>(b1, Wmu, Wlog, N);

    // layer 2 aggregation writes d_out directly
    k_agg2_csr<<<gW, T>>>(bmu, blog, outMu, outLog, N);
}

// round 15
// speedup vs baseline: 1.1936x; 1.1936x over previous
#include <cuda_runtime.h>
#include <cuda_fp16.h>

// Problem-fixed dims: N=100000, E=1600000, IN=128, H=64, OUT=32
#define MAXN 100000
#define MAXE 1600000
#define IN_DIM 128
#define H_DIM 64
#define OUT_DIM 32
#define SCAN_B 1024
#define MAX_BLK ((MAXN + SCAN_B - 1) / SCAN_B)   // 98

typedef unsigned long long ull;

// ---------------- scratch (device globals; no allocation allowed) ------------
__device__ __align__(16) int   g_cnt [MAXN];   // in-degree; zero at module load,
                                               // re-zeroed by k_scatter each run
__device__ __align__(16) int   g_row [MAXN + 1];
__device__ __align__(16) int   g_cur [MAXN];
__device__ __align__(16) int   g_bsum[MAX_BLK];
__device__ __align__(16) int   g_boff[MAX_BLK];
__device__ __align__(16) float g_dinv[MAXN];
__device__ __align__(16) int2  g_csr [MAXE];   // (src, norm-bits) grouped by dst
__device__ __align__(16) __half g_Z1h[(size_t)MAXN * H_DIM]; // x@W1      (fp16)
__device__ __align__(16) float  g_h [(size_t)MAXN * H_DIM];  // conv1 out (fp32)
__device__ __align__(16) __half g_Z2h[(size_t)MAXN * H_DIM]; // relu(h)@W (fp16)

// ---------------- bit-cast helpers -------------------------------------------
__device__ __forceinline__ unsigned h2u(__half2 h) {
    return *reinterpret_cast<unsigned*>(&h);
}
__device__ __forceinline__ __half2 u2h(unsigned u) {
    return *reinterpret_cast<__half2*>(&u);
}

// ---------------- f32x2 packed FMA helpers -----------------------------------
__device__ __forceinline__ ull pack_dup(float a) {
    ull r;
    asm("mov.b64 %0, {%1, %1};" : "=l"(r) : "r"(__float_as_uint(a)));
    return r;
}
#define FMA2(acc, a2, b2) \
    asm("fma.rn.f32x2 %0, %1, %2, %0;" : "+l"(acc) : "l"(a2), "l"(b2))

__device__ __forceinline__ float2 unpack2(ull v) {
    float2 f;
    asm("mov.b64 {%0, %1}, %2;" : "=f"(f.x), "=f"(f.y) : "l"(v));
    return f;
}

// Convert 32 packed-f32x2 accumulators to a 64-col fp16 row and store.
__device__ __forceinline__ void store_row_fp16(__half* dst, const ull* acc) {
    uint4* crow = (uint4*)dst;
#pragma unroll
    for (int q = 0; q < 8; q++) {
        uint4 v;
        float2 f0 = unpack2(acc[4 * q + 0]);
        float2 f1 = unpack2(acc[4 * q + 1]);
        float2 f2 = unpack2(acc[4 * q + 2]);
        float2 f3 = unpack2(acc[4 * q + 3]);
        v.x = h2u(__floats2half2_rn(f0.x, f0.y));
        v.y = h2u(__floats2half2_rn(f1.x, f1.y));
        v.z = h2u(__floats2half2_rn(f2.x, f2.y));
        v.w = h2u(__floats2half2_rn(f3.x, f3.y));
        crow[q] = v;
    }
}

// ---------------- dtype probe helper (per-block, L2-hot, ~free) --------------
__device__ __forceinline__ int probe_is64(const int* __restrict__ raw, int E,
                                          int* sh_nz) {
    if (threadIdx.x == 0) *sh_nz = 0;
    __syncthreads();
    int K = 2048;
    if (K > 2 * E) K = 2 * E;
    int cnt = 0;
    for (int i = 2 * threadIdx.x + 1; i < K; i += 2 * blockDim.x)
        if (raw[i] != 0) cnt++;
    if (cnt) atomicAdd(sh_nz, cnt);
    __syncthreads();
    return (*sh_nz == 0);
}

// ---------------- count in-degrees straight from raw edge list ---------------
__global__ __launch_bounds__(256) void k_count(const int* __restrict__ raw,
                                               int E, int n) {
    __shared__ int nz;
    int is64 = probe_is64(raw, E, &nz);
    int i = blockIdx.x * 256 + threadIdx.x;
    if (i >= E) return;
    int d = is64 ? (int)((const long long*)raw)[(size_t)E + i] : raw[E + i];
    if ((unsigned)d >= (unsigned)n) d = 0;
    atomicAdd(&g_cnt[d], 1);
}

// ---------------- hierarchical exclusive scan of g_cnt -----------------------
__global__ __launch_bounds__(SCAN_B) void k_scanA(int n) {
    __shared__ int sh[SCAN_B];
    int t = threadIdx.x;
    int i = blockIdx.x * SCAN_B + t;
    int v = (i < n) ? g_cnt[i] : 0;
    sh[t] = v;
    __syncthreads();
#pragma unroll
    for (int off = 1; off < SCAN_B; off <<= 1) {
        int u = (t >= off) ? sh[t - off] : 0;
        __syncthreads();
        sh[t] += u;
        __syncthreads();
    }
    if (i < n) g_row[i] = sh[t] - v;
    if (t == SCAN_B - 1) g_bsum[blockIdx.x] = sh[t];
}

__global__ __launch_bounds__(128) void k_scanB(int nblk, int n) {
    __shared__ int sh[128];
    int t = threadIdx.x;
    int v = (t < nblk) ? g_bsum[t] : 0;
    sh[t] = v;
    __syncthreads();
#pragma unroll
    for (int off = 1; off < 128; off <<= 1) {
        int u = (t >= off) ? sh[t - off] : 0;
        __syncthreads();
        sh[t] += u;
        __syncthreads();
    }
    if (t < nblk) g_boff[t] = sh[t] - v;
    if (t == 127) g_row[n] = sh[127];
}

// Phase C: add block offsets; mirror into g_cur; fused dinv.
__global__ __launch_bounds__(SCAN_B) void k_scanC(int n) {
    int i = blockIdx.x * SCAN_B + threadIdx.x;
    if (i < n) {
        int r = g_row[i] + g_boff[blockIdx.x];
        g_row[i] = r;
        g_cur[i] = r;
        g_dinv[i] = rsqrtf(1.0f + (float)g_cnt[i]);  // +1 self-loop
    }
}

// ---------------- scatter into CSR; also reset g_cnt for next replay ---------
__global__ __launch_bounds__(256) void k_scatter(const int* __restrict__ raw,
                                                 int E, int n) {
    __shared__ int nz;
    int is64 = probe_is64(raw, E, &nz);
    int i = blockIdx.x * 256 + threadIdx.x;
    if (i < n) g_cnt[i] = 0;       // g_cnt no longer needed this run
    if (i >= E) return;
    int s, d;
    if (is64) {
        const long long* e64 = (const long long*)raw;
        s = (int)e64[i];
        d = (int)e64[(size_t)E + i];
    } else {
        s = raw[i];
        d = raw[E + i];
    }
    if ((unsigned)s >= (unsigned)n) s = 0;
    if ((unsigned)d >= (unsigned)n) d = 0;
    float w = g_dinv[s] * g_dinv[d];
    int pos = atomicAdd(&g_cur[d], 1);
    g_csr[pos] = make_int2(s, __float_as_int(w));
}

// ---------------- GEMM1: Z1 = x @ W1, 2 rows/thread, fp16 store --------------
__global__ __launch_bounds__(128) void k_gemm1(const float* __restrict__ x,
                                               const float* __restrict__ W1, int n) {
    __shared__ __align__(16) float Bs[IN_DIM * H_DIM];  // 32 KB
    int tid = threadIdx.x;
    for (int i = tid; i < IN_DIM * H_DIM; i += 128) Bs[i] = W1[i];
    __syncthreads();
    int rA = blockIdx.x * 256 + tid;
    if (rA >= n) return;
    int rB = rA + 128;
    bool hasB = (rB < n);

    ull accA[32], accB[32];
#pragma unroll
    for (int i = 0; i < 32; i++) { accA[i] = 0ull; accB[i] = 0ull; }

    const float4* aA = (const float4*)(x + (size_t)rA * IN_DIM);
    const float4* aB = (const float4*)(x + (size_t)(hasB ? rB : rA) * IN_DIM);
    for (int k4 = 0; k4 < IN_DIM / 4; k4++) {
        float4 a4A = aA[k4];
        float4 a4B = aB[k4];
        float avA[4] = {a4A.x, a4A.y, a4A.z, a4A.w};
        float avB[4] = {a4B.x, a4B.y, a4B.z, a4B.w};
#pragma unroll
        for (int kk = 0; kk < 4; kk++) {
            ull a2A = pack_dup(avA[kk]);
            ull a2B = pack_dup(avB[kk]);
            const ull* br = (const ull*)(Bs + (k4 * 4 + kk) * H_DIM);
#pragma unroll
            for (int c = 0; c < 32; c++) {
                ull b = br[c];                 // one LDS feeds two rows
                FMA2(accA[c], a2A, b);
                FMA2(accB[c], a2B, b);
            }
        }
    }
    store_row_fp16(g_Z1h + (size_t)rA * H_DIM, accA);
    if (hasB) store_row_fp16(g_Z1h + (size_t)rB * H_DIM, accB);
}

// ---------------- CSR aggregation 1: warp/node, fp16 gather, fp32 acc --------
__global__ __launch_bounds__(256) void k_agg1_csr(const float* __restrict__ b1, int n) {
    int warp = (blockIdx.x * 256 + threadIdx.x) >> 5;
    int lane = threadIdx.x & 31;
    if (warp >= n) return;
    int half = lane >> 4, l16 = lane & 15;
    int rs = g_row[warp], re = g_row[warp + 1];
    const uint2* zb = (const uint2*)g_Z1h;   // uint2 = 4 halves = 4 cols

    float4 acc;
    if (half == 0) {   // seed self-loop + bias once
        float dv = g_dinv[warp];
        float s2 = dv * dv;
        uint2 z = zb[(size_t)warp * 16 + l16];
        float2 f0 = __half22float2(u2h(z.x));
        float2 f1 = __half22float2(u2h(z.y));
        float4 b  = ((const float4*)b1)[l16];
        acc = make_float4(fmaf(f0.x, s2, b.x), fmaf(f0.y, s2, b.y),
                          fmaf(f1.x, s2, b.z), fmaf(f1.y, s2, b.w));
    } else {
        acc = make_float4(0.f, 0.f, 0.f, 0.f);
    }
    for (int e = rs + half; e < re; e += 2) {
        int2 ed = g_csr[e];
        float w = __int_as_float(ed.y);
        uint2 z = zb[(size_t)ed.x * 16 + l16];
        float2 f0 = __half22float2(u2h(z.x));
        float2 f1 = __half22float2(u2h(z.y));
        acc.x = fmaf(w, f0.x, acc.x);
        acc.y = fmaf(w, f0.y, acc.y);
        acc.z = fmaf(w, f1.x, acc.z);
        acc.w = fmaf(w, f1.y, acc.w);
    }
    acc.x += __shfl_xor_sync(0xffffffffu, acc.x, 16);
    acc.y += __shfl_xor_sync(0xffffffffu, acc.y, 16);
    acc.z += __shfl_xor_sync(0xffffffffu, acc.z, 16);
    acc.w += __shfl_xor_sync(0xffffffffu, acc.w, 16);
    if (half == 0)
        ((float4*)g_h)[(size_t)warp * 16 + l16] = acc;
}

// ---------------- GEMM2: Z2 = relu(h) @ [Wmu|Wlog], 2 rows/thread ------------
__global__ __launch_bounds__(128) void k_gemm2(const float* __restrict__ Wmu,
                                               const float* __restrict__ Wlog, int n) {
    __shared__ __align__(16) float Bs[H_DIM * 64];  // cols 0..31 Wmu, 32..63 Wlog
    int tid = threadIdx.x;
    for (int i = tid; i < H_DIM * OUT_DIM; i += 128) {
        int k = i / OUT_DIM, c = i % OUT_DIM;
        Bs[k * 64 + c]      = Wmu[i];
        Bs[k * 64 + 32 + c] = Wlog[i];
    }
    __syncthreads();
    int rA = blockIdx.x * 256 + tid;
    if (rA >= n) return;
    int rB = rA + 128;
    bool hasB = (rB < n);

    ull accA[32], accB[32];
#pragma unroll
    for (int i = 0; i < 32; i++) { accA[i] = 0ull; accB[i] = 0ull; }

    const float4* aA = (const float4*)(g_h + (size_t)rA * H_DIM);
    const float4* aB = (const float4*)(g_h + (size_t)(hasB ? rB : rA) * H_DIM);
    for (int k4 = 0; k4 < H_DIM / 4; k4++) {
        float4 a4A = aA[k4];
        float4 a4B = aB[k4];
        float avA[4] = {fmaxf(a4A.x, 0.f), fmaxf(a4A.y, 0.f),
                        fmaxf(a4A.z, 0.f), fmaxf(a4A.w, 0.f)};
        float avB[4] = {fmaxf(a4B.x, 0.f), fmaxf(a4B.y, 0.f),
                        fmaxf(a4B.z, 0.f), fmaxf(a4B.w, 0.f)};
#pragma unroll
        for (int kk = 0; kk < 4; kk++) {
            ull a2A = pack_dup(avA[kk]);
            ull a2B = pack_dup(avB[kk]);
            const ull* br = (const ull*)(Bs + (k4 * 4 + kk) * 64);
#pragma unroll
            for (int c = 0; c < 32; c++) {
                ull b = br[c];
                FMA2(accA[c], a2A, b);
                FMA2(accB[c], a2B, b);
            }
        }
    }
    store_row_fp16(g_Z2h + (size_t)rA * H_DIM, accA);
    if (hasB) store_row_fp16(g_Z2h + (size_t)rB * H_DIM, accB);
}

// ---------------- CSR aggregation 2: warp/node, fp16 gather -> d_out ---------
__global__ __launch_bounds__(256) void k_agg2_csr(const float* __restrict__ bmu,
                                                  const float* __restrict__ blog,
                                                  float* __restrict__ outMu,
                                                  float* __restrict__ outLog, int n) {
    int warp = (blockIdx.x * 256 + threadIdx.x) >> 5;
    int lane = threadIdx.x & 31;
    if (warp >= n) return;
    int half = lane >> 4, l16 = lane & 15;
    int rs = g_row[warp], re = g_row[warp + 1];
    const uint2* zb = (const uint2*)g_Z2h;

    float4 acc;
    if (half == 0) {
        float dv = g_dinv[warp];
        float s2 = dv * dv;
        uint2 z = zb[(size_t)warp * 16 + l16];
        float2 f0 = __half22float2(u2h(z.x));
        float2 f1 = __half22float2(u2h(z.y));
        float4 b = (l16 < 8) ? ((const float4*)bmu)[l16]
                             : ((const float4*)blog)[l16 - 8];
        acc = make_float4(fmaf(f0.x, s2, b.x), fmaf(f0.y, s2, b.y),
                          fmaf(f1.x, s2, b.z), fmaf(f1.y, s2, b.w));
    } else {
        acc = make_float4(0.f, 0.f, 0.f, 0.f);
    }
    for (int e = rs + half; e < re; e += 2) {
        int2 ed = g_csr[e];
        float w = __int_as_float(ed.y);
        uint2 z = zb[(size_t)ed.x * 16 + l16];
        float2 f0 = __half22float2(u2h(z.x));
        float2 f1 = __half22float2(u2h(z.y));
        acc.x = fmaf(w, f0.x, acc.x);
        acc.y = fmaf(w, f0.y, acc.y);
        acc.z = fmaf(w, f1.x, acc.z);
        acc.w = fmaf(w, f1.y, acc.w);
    }
    acc.x += __shfl_xor_sync(0xffffffffu, acc.x, 16);
    acc.y += __shfl_xor_sync(0xffffffffu, acc.y, 16);
    acc.z += __shfl_xor_sync(0xffffffffu, acc.z, 16);
    acc.w += __shfl_xor_sync(0xffffffffu, acc.w, 16);
    if (half == 0) {
        if (l16 < 8)
            ((float4*)(outMu + (size_t)warp * OUT_DIM))[l16] = acc;
        else
            ((float4*)(outLog + (size_t)warp * OUT_DIM))[l16 - 8] = acc;
    }
}

// ---------------- launch -----------------------------------------------------
extern "C" void kernel_launch(void* const* d_in, const int* in_sizes, int n_in,
                              void* d_out, int out_size) {
    const float* x    = (const float*)d_in[0];
    const int*   eraw = (const int*)d_in[1];
    const float* W1   = (const float*)d_in[2];
    const float* b1   = (const float*)d_in[3];
    const float* Wmu  = (const float*)d_in[4];
    const float* bmu  = (const float*)d_in[5];
    const float* Wlog = (const float*)d_in[6];
    const float* blog = (const float*)d_in[7];

    int N = in_sizes[0] / IN_DIM;   // 100000
    int E = in_sizes[1] / 2;        // 1600000
    if (N > MAXN) N = MAXN;
    if (E > MAXE) E = MAXE;

    float* outMu  = (float*)d_out;
    float* outLog = (float*)d_out + (size_t)N * OUT_DIM;

    const int T = 256;
    int gE   = (E + T - 1) / T;
    int gW   = (N * 32 + T - 1) / T;          // warp-per-node grids
    int gG   = (N + 255) / 256;               // 2-row GEMM grids (128 threads)
    int nblk = (N + SCAN_B - 1) / SCAN_B;     // scan blocks (98)

    // Lazy side-stream + fork/join events (host objects only).
    static cudaStream_t s2 = nullptr;
    static cudaEvent_t  evFork = nullptr, evJoin = nullptr;
    if (s2 == nullptr) {
        cudaStreamCreateWithFlags(&s2, cudaStreamNonBlocking);
        cudaEventCreateWithFlags(&evFork, cudaEventDisableTiming);
        cudaEventCreateWithFlags(&evJoin, cudaEventDisableTiming);
    }

    // Fork: GEMM1 runs concurrently with the CSR build chain.
    cudaEventRecord(evFork, 0);
    cudaStreamWaitEvent(s2, evFork, 0);
    k_gemm1<<<gG, 128, 0, s2>>>(x, W1, N);
    cudaEventRecord(evJoin, s2);

    // CSR build on the main stream (g_cnt zeroed by previous run's k_scatter;
    // zero-initialized at module load for the first run)
    k_count<<<gE, T>>>(eraw, E, N);
    k_scanA<<<nblk, SCAN_B>>>(N);
    k_scanB<<<1, 128>>>(nblk, N);
    k_scanC<<<nblk, SCAN_B>>>(N);             // offsets + g_cur + dinv fused
    k_scatter<<<gE, T>>>(eraw, E, N);         // also resets g_cnt

    // Join: agg1 needs both Z1 (s2) and CSR (main stream)
    cudaStreamWaitEvent(0, evJoin, 0);

    // layer 1 aggregation
    k_agg1_csr<<<gW, T>>>(b1, N);

    // layer 2 (mu|log fused), aggregation writes d_out directly
    k_gemm2<<<gG, 128>>>(Wmu, Wlog, N);
    k_agg2_csr<<<gW, T>>>(bmu, blog, outMu, outLog, N);
}